// round 11
// baseline (speedup 1.0000x reference)
#include <cuda_runtime.h>
#include <math.h>
#include <stdint.h>

#define BB 4
#define NQ 64
#define NN 1024
#define DD 768
#define HH 8
#define DH 96
#define RANK 64
#define QR 4096
#define LN_EPS 1e-5f

// ---------------- scratch (static device allocations; no cudaMalloc) ----------------
__device__ float g_q  [BB*NQ*DD];
__device__ float g_k  [BB*NN*DD];              // 12.6 MB
__device__ float g_sim[(size_t)BB*HH*NQ*NN];   // 8.4 MB (attn, then w = attn*inv)
__device__ float g_mu [BB*NN];
__device__ float g_inv[BB*NN];
__device__ float g_s  [BB*HH*NQ];
__device__ float g_u  [(size_t)BB*HH*NQ*DD];   // 6.3 MB
__device__ float g_t  [BB*NQ*HH*RANK];
__device__ float g_op [BB*NQ*DD];

// tf32-rounded operands
__device__ float g_ctx32[(size_t)BB*NN*DD];    // 12.6 MB
__device__ float g_x32  [BB*NQ*DD];
__device__ float g_Wq32 [DD*DD];
__device__ float g_Wk32 [DD*DD];
__device__ float g_Wv32 [(size_t)DD*QR];       // 12.6 MB (rounded Wv1, [768][4096])
__device__ float g_Wo32 [DD*DD];
__device__ float g_Wv1T [(size_t)QR*DD];       // 12.6 MB (rounded Wv1^T, [4096][768])
__device__ float g_rs   [DD];                  // rowsum of Wv1 (original)
__device__ float g_Gp   [(size_t)4*DD*DD];     // split-K partials of G
__device__ float g_G32  [DD*DD];               // G = Wv1 Wv1^T (tf32-rounded)
__device__ float g_y    [(size_t)BB*NN*DD];    // 12.6 MB  y = ctx @ G

// ---------------- helpers ----------------
__device__ __forceinline__ uint32_t s2u(const void* p) {
    return (uint32_t)__cvta_generic_to_shared(p);
}
__device__ __forceinline__ float to_tf32(float x) {
    uint32_t u;
    asm("cvt.rna.tf32.f32 %0, %1;" : "=r"(u) : "f"(x));
    return __uint_as_float(u);
}
__device__ __forceinline__ void cp16(uint32_t dst, const void* src) {
    asm volatile("cp.async.cg.shared.global [%0], [%1], 16;" :: "r"(dst), "l"(src) : "memory");
}
__device__ __forceinline__ void mma_tf32(float* d, const uint32_t* a, const uint32_t* b) {
    asm volatile("mma.sync.aligned.m16n8k8.row.col.f32.tf32.tf32.f32 "
                 "{%0,%1,%2,%3}, {%4,%5,%6,%7}, {%8,%9}, {%0,%1,%2,%3};"
                 : "+f"(d[0]), "+f"(d[1]), "+f"(d[2]), "+f"(d[3])
                 : "r"(a[0]), "r"(a[1]), "r"(a[2]), "r"(a[3]),
                   "r"(b[0]), "r"(b[1]));
}

// ---------------- tf32 GEMM, cp.async 2-stage, 2 CTAs/SM, z-batched ----------------
// C[M][Nn] = A[M][K] @ B[K][Nn]; inputs pre-rounded to tf32.  M%BM==0, Nn%128==0, K%32==0.
template<int BM>
__global__ void __launch_bounds__(256, 2) tgemm_ca(const float* __restrict__ A,
                                                   const float* __restrict__ Bm,
                                                   float* __restrict__ C,
                                                   int Nn, int K, int lda, int ldb, int ldc,
                                                   size_t sA, size_t sB, size_t sC)
{
    constexpr int WCOLS = (BM == 128) ? 2 : 4;
    constexpr int WN    = 128 / WCOLS;
    constexpr int NI    = WN / 8;
    constexpr int ASZ   = BM * 36;
    constexpr int BSZ   = 32 * 136;
    constexpr int STG   = ASZ + BSZ;
    constexpr int ALD   = BM * 8 / 256;

    extern __shared__ float sm[];

    A  += blockIdx.z * sA;
    Bm += blockIdx.z * sB;
    C  += blockIdx.z * sC;

    int tid = threadIdx.x;
    int warp = tid >> 5, lane = tid & 31;
    int g = lane >> 2, tg = lane & 3;
    int wm = (warp / WCOLS) * 32;
    int wn = (warp % WCOLS) * WN;
    int m0 = blockIdx.y * BM, n0 = blockIdx.x * 128;

    float acc[2][NI][4];
    #pragma unroll
    for (int mi = 0; mi < 2; mi++)
        #pragma unroll
        for (int ni = 0; ni < NI; ni++)
            #pragma unroll
            for (int c = 0; c < 4; c++) acc[mi][ni][c] = 0.f;

    int nk = K >> 5;

    auto fill = [&](int stage, int kt) {
        uint32_t asb = s2u(sm + stage * STG);
        uint32_t bsb = asb + ASZ * 4;
        #pragma unroll
        for (int l = 0; l < ALD; l++) {
            int seg = tid + l * 256;
            int row = seg >> 3, sc = seg & 7;
            cp16(asb + (uint32_t)(row * 144 + sc * 16),
                 A + (size_t)(m0 + row) * lda + kt + sc * 4);
        }
        #pragma unroll
        for (int l = 0; l < 4; l++) {
            int seg = tid + l * 256;
            int row = seg >> 5, sc = seg & 31;
            cp16(bsb + (uint32_t)(row * 544 + sc * 16),
                 Bm + (size_t)(kt + row) * ldb + n0 + sc * 4);
        }
    };

    fill(0, 0);
    asm volatile("cp.async.commit_group;" ::: "memory");
    fill(1, 32);
    asm volatile("cp.async.commit_group;" ::: "memory");

    for (int it = 0; it < nk; it++) {
        asm volatile("cp.async.wait_group 1;" ::: "memory");
        __syncthreads();
        int s = it & 1;
        const float* As = sm + s * STG;
        const float* Bs = As + ASZ;

        #pragma unroll
        for (int ks = 0; ks < 4; ks++) {
            int kk = ks * 8;
            uint32_t af[2][4], bf[NI][2];
            #pragma unroll
            for (int mi = 0; mi < 2; mi++) {
                int mr = wm + mi * 16 + g;
                af[mi][0] = __float_as_uint(As[ mr      * 36 + kk + tg    ]);
                af[mi][1] = __float_as_uint(As[(mr + 8) * 36 + kk + tg    ]);
                af[mi][2] = __float_as_uint(As[ mr      * 36 + kk + tg + 4]);
                af[mi][3] = __float_as_uint(As[(mr + 8) * 36 + kk + tg + 4]);
            }
            #pragma unroll
            for (int ni = 0; ni < NI; ni++) {
                int nc = wn + ni * 8 + g;
                bf[ni][0] = __float_as_uint(Bs[(kk + tg    ) * 136 + nc]);
                bf[ni][1] = __float_as_uint(Bs[(kk + tg + 4) * 136 + nc]);
            }
            #pragma unroll
            for (int mi = 0; mi < 2; mi++)
                #pragma unroll
                for (int ni = 0; ni < NI; ni++)
                    mma_tf32(acc[mi][ni], af[mi], bf[ni]);
        }

        // refill the stage we just consumed (needs a barrier: other warps may lag)
        __syncthreads();
        if (it + 2 < nk) fill(s, (it + 2) * 32);
        asm volatile("cp.async.commit_group;" ::: "memory");
    }

    #pragma unroll
    for (int mi = 0; mi < 2; mi++) {
        int r0 = m0 + wm + mi * 16 + g;
        #pragma unroll
        for (int ni = 0; ni < NI; ni++) {
            int c = n0 + wn + ni * 8 + 2 * tg;
            *(float2*)(C + (size_t)r0 * ldc + c)       = make_float2(acc[mi][ni][0], acc[mi][ni][1]);
            *(float2*)(C + (size_t)(r0 + 8) * ldc + c) = make_float2(acc[mi][ni][2], acc[mi][ni][3]);
        }
    }
}

// ---------------- tf32 rounding prepass ----------------
__global__ __launch_bounds__(256) void cvt_tf32(const float* __restrict__ in,
                                                float* __restrict__ outp)
{
    size_t i = (size_t)blockIdx.x * 256 + threadIdx.x;
    float4 v = ((const float4*)in)[i];
    v.x = to_tf32(v.x); v.y = to_tf32(v.y);
    v.z = to_tf32(v.z); v.w = to_tf32(v.w);
    ((float4*)outp)[i] = v;
}

// three 768x768 weights in one launch (z selects)
__global__ __launch_bounds__(256) void cvt_tf32_3(const float* __restrict__ i0, float* o0,
                                                  const float* __restrict__ i1, float* o1,
                                                  const float* __restrict__ i2, float* o2)
{
    const float* in = (blockIdx.y == 0) ? i0 : (blockIdx.y == 1) ? i1 : i2;
    float* outp     = (blockIdx.y == 0) ? o0 : (blockIdx.y == 1) ? o1 : o2;
    size_t i = (size_t)blockIdx.x * 256 + threadIdx.x;
    float4 v = ((const float4*)in)[i];
    v.x = to_tf32(v.x); v.y = to_tf32(v.y);
    v.z = to_tf32(v.z); v.w = to_tf32(v.w);
    ((float4*)outp)[i] = v;
}

// ---------------- Wv1 [768][4096] -> Wv1T [4096][768] (tf32-rounded) ----------------
__global__ __launch_bounds__(256) void trans_round(const float* __restrict__ W)
{
    __shared__ float tile[32][33];
    int c0 = blockIdx.x * 32, d0 = blockIdx.y * 32;
    int tid = threadIdx.x;
    int r = tid >> 5, cl = tid & 31;
    #pragma unroll
    for (int p = 0; p < 4; p++)
        tile[r + p * 8][cl] = W[(size_t)(d0 + r + p * 8) * QR + c0 + cl];
    __syncthreads();
    #pragma unroll
    for (int p = 0; p < 4; p++)
        g_Wv1T[(size_t)(c0 + r + p * 8) * DD + d0 + cl] = to_tf32(tile[cl][r + p * 8]);
}

// ---------------- rs[d] = sum_c Wv1[d][c]  (warp per row) ----------------
__global__ __launch_bounds__(256) void rowsum(const float* __restrict__ W)
{
    int row = blockIdx.x * 8 + (threadIdx.x >> 5);
    int lane = threadIdx.x & 31;
    const float* p = W + (size_t)row * QR;
    float s = 0.f;
    for (int c = lane; c < QR; c += 32) s += p[c];
    #pragma unroll
    for (int o = 16; o > 0; o >>= 1) s += __shfl_xor_sync(0xFFFFFFFF, s, o);
    if (lane == 0) g_rs[row] = s;
}

// ---------------- G = sum of 4 split-K partials, tf32-rounded ----------------
__global__ __launch_bounds__(256) void reduce4()
{
    size_t i = (size_t)blockIdx.x * 256 + threadIdx.x;
    const float4* P = (const float4*)g_Gp;
    size_t st = (size_t)DD * DD / 4;
    float4 a = P[i], b = P[i + st], c = P[i + 2 * st], d = P[i + 3 * st];
    float4 o;
    o.x = to_tf32(a.x + b.x + c.x + d.x);
    o.y = to_tf32(a.y + b.y + c.y + d.y);
    o.z = to_tf32(a.z + b.z + c.z + d.z);
    o.w = to_tf32(a.w + b.w + c.w + d.w);
    ((float4*)g_G32)[i] = o;
}

// ---------------- stats: mu_j = ctx_j . rs / 4096 ; inv_j from ctx_j . y_j ----------
__global__ __launch_bounds__(256) void stats(const float* __restrict__ ctx)
{
    int row  = blockIdx.x * 8 + (threadIdx.x >> 5);   // 512 blocks -> 4096 rows
    int lane = threadIdx.x & 31;
    const float* cr = ctx + (size_t)row * DD;
    const float* yr = g_y + (size_t)row * DD;
    float md = 0.f, ed = 0.f;
    for (int d = lane; d < DD; d += 32) {
        float c = cr[d];
        md += c * g_rs[d];
        ed += c * yr[d];
    }
    #pragma unroll
    for (int o = 16; o > 0; o >>= 1) {
        md += __shfl_xor_sync(0xFFFFFFFF, md, o);
        ed += __shfl_xor_sync(0xFFFFFFFF, ed, o);
    }
    if (lane == 0) {
        float mu = md * (1.0f / QR);
        float e2 = ed * (1.0f / QR);
        g_mu[row]  = mu;
        g_inv[row] = rsqrtf(e2 - mu * mu + LN_EPS);
    }
}

// ---------------- sim[b,h,i,j] = (1/sqrt(dh)) q.k ----------------
__global__ __launch_bounds__(256) void sim_kernel()
{
    __shared__ float qs[64][97];
    __shared__ float ks[32][97];
    int jt = blockIdx.x, h = blockIdx.y, b = blockIdx.z;
    int tid = threadIdx.x;

    for (int idx = tid; idx < 64 * 96; idx += 256) {
        int i = idx / 96, c = idx % 96;
        qs[i][c] = g_q[(size_t)(b * NQ + i) * DD + h * DH + c];
    }
    for (int idx = tid; idx < 32 * 96; idx += 256) {
        int j = idx / 96, c = idx % 96;
        ks[j][c] = g_k[(size_t)(b * NN + jt * 32 + j) * DD + h * DH + c];
    }
    __syncthreads();

    int tx = tid & 15, ty = tid >> 4;
    float acc[4][2];
    #pragma unroll
    for (int ii = 0; ii < 4; ii++) { acc[ii][0] = 0.f; acc[ii][1] = 0.f; }

    #pragma unroll 4
    for (int c = 0; c < 96; c++) {
        float qv[4], kv[2];
        #pragma unroll
        for (int ii = 0; ii < 4; ii++) qv[ii] = qs[ty * 4 + ii][c];
        kv[0] = ks[tx * 2][c];
        kv[1] = ks[tx * 2 + 1][c];
        #pragma unroll
        for (int ii = 0; ii < 4; ii++) {
            acc[ii][0] = fmaf(qv[ii], kv[0], acc[ii][0]);
            acc[ii][1] = fmaf(qv[ii], kv[1], acc[ii][1]);
        }
    }

    const float sc = 0.10206207261596577f;
    #pragma unroll
    for (int ii = 0; ii < 4; ii++)
        #pragma unroll
        for (int jj = 0; jj < 2; jj++) {
            int i = ty * 4 + ii, j = jt * 32 + tx * 2 + jj;
            g_sim[((size_t)(b * HH + h) * NQ + i) * NN + j] = acc[ii][jj] * sc;
        }
}

// -------- softmax + fold: w = tf32(attn*inv_j) in place; s[row] = sum attn*inv*mu ---
__global__ __launch_bounds__(256) void softmax_w()
{
    int row = blockIdx.x;          // (b*8+h)*64+i
    int b = row >> 9;
    float4* p = (float4*)(g_sim + (size_t)row * NN);
    __shared__ float red[256];
    int tid = threadIdx.x;

    float4 v = p[tid];
    float m = fmaxf(fmaxf(v.x, v.y), fmaxf(v.z, v.w));
    red[tid] = m; __syncthreads();
    for (int o = 128; o > 0; o >>= 1) {
        if (tid < o) red[tid] = fmaxf(red[tid], red[tid + o]);
        __syncthreads();
    }
    m = red[0]; __syncthreads();

    v.x = __expf(v.x - m); v.y = __expf(v.y - m);
    v.z = __expf(v.z - m); v.w = __expf(v.w - m);
    red[tid] = v.x + v.y + v.z + v.w; __syncthreads();
    for (int o = 128; o > 0; o >>= 1) {
        if (tid < o) red[tid] += red[tid + o];
        __syncthreads();
    }
    float invs = 1.0f / red[0];
    __syncthreads();

    float4 mu4 = ((const float4*)(g_mu  + b * NN))[tid];
    float4 iv4 = ((const float4*)(g_inv + b * NN))[tid];
    float4 w;
    w.x = v.x * invs * iv4.x; w.y = v.y * invs * iv4.y;
    w.z = v.z * invs * iv4.z; w.w = v.w * invs * iv4.w;
    float sacc = w.x * mu4.x + w.y * mu4.y + w.z * mu4.z + w.w * mu4.w;
    w.x = to_tf32(w.x); w.y = to_tf32(w.y);
    w.z = to_tf32(w.z); w.w = to_tf32(w.w);
    p[tid] = w;

    red[tid] = sacc; __syncthreads();
    for (int o = 128; o > 0; o >>= 1) {
        if (tid < o) red[tid] += red[tid + o];
        __syncthreads();
    }
    if (tid == 0) g_s[row] = red[0];
}

// ---- t[b,i,h,r] = gam[ir]*( sum_d u[b,h,i,d]*Wv1T[ir][d] - s[b,h,i] ) + bet[ir] ----
// one block per i; loop over b so each Wv1T slice (196 KB) is read once into L2
__global__ __launch_bounds__(256) void tfin_kernel(const float* __restrict__ gam,
                                                   const float* __restrict__ bet)
{
    int i = blockIdx.x;              // 0..63
    __shared__ float u_s[HH][DD];    // 24 KB
    int tid = threadIdx.x;
    int warp = tid >> 5, lane = tid & 31;

    for (int b = 0; b < BB; b++) {
        for (int idx = tid; idx < HH * DD; idx += 256) {
            int h = idx / DD, d = idx % DD;
            u_s[h][d] = g_u[((size_t)b * 512 + h * 64 + i) * DD + d];
        }
        __syncthreads();

        #pragma unroll
        for (int rr = 0; rr < 8; rr++) {
            int r = warp * 8 + rr;
            const float* wv = g_Wv1T + (size_t)(i * RANK + r) * DD;
            float a[8];
            #pragma unroll
            for (int h = 0; h < 8; h++) a[h] = 0.f;
            for (int d = lane; d < DD; d += 32) {
                float wvv = wv[d];
                #pragma unroll
                for (int h = 0; h < 8; h++) a[h] = fmaf(u_s[h][d], wvv, a[h]);
            }
            #pragma unroll
            for (int o = 16; o > 0; o >>= 1)
                #pragma unroll
                for (int h = 0; h < 8; h++) a[h] += __shfl_xor_sync(0xFFFFFFFF, a[h], o);
            if (lane == 0) {
                float gm = gam[i * RANK + r], bt = bet[i * RANK + r];
                #pragma unroll
                for (int h = 0; h < 8; h++) {
                    float sv = g_s[(b * HH + h) * NQ + i];
                    g_t[((size_t)(b * NQ + i) * HH + h) * RANK + r] = gm * (a[h] - sv) + bt;
                }
            }
        }
        __syncthreads();
    }
}

// ---- out_pre[b,i,d] = sum_r t[b,i,head(d),r]*Wc[i,r,d]  (tf32-rounded write) ------
__global__ __launch_bounds__(256) void conv_kernel(const float* __restrict__ Wc)
{
    int b = blockIdx.x >> 6, i = blockIdx.x & 63;
    __shared__ float ts[HH * RANK];
    int tid = threadIdx.x;
    for (int idx = tid; idx < HH * RANK; idx += 256)
        ts[idx] = g_t[(size_t)(b * NQ + i) * (HH * RANK) + idx];
    __syncthreads();

    for (int dd = tid; dd < DD; dd += 256) {
        int h = dd / DH;
        float acc = 0.f;
        const float* wp = Wc + (size_t)i * RANK * DD + dd;
        #pragma unroll 8
        for (int rr = 0; rr < RANK; rr++)
            acc = fmaf(ts[h * RANK + rr], wp[(size_t)rr * DD], acc);
        g_op[(size_t)(b * NQ + i) * DD + dd] = to_tf32(acc);
    }
}

// ---------------- launch ----------------
#define SMEM128 (2 * (128 * 36 + 32 * 136) * 4)   // 71680
#define SMEM64  (2 * ( 64 * 36 + 32 * 136) * 4)   // 53248

extern "C" void kernel_launch(void* const* d_in, const int* in_sizes, int n_in,
                              void* d_out, int out_size)
{
    const float* x       = (const float*)d_in[0];
    const float* context = (const float*)d_in[1];
    const float* Wq      = (const float*)d_in[2];
    const float* Wk      = (const float*)d_in[3];
    const float* Wv1     = (const float*)d_in[4];
    const float* ln_g    = (const float*)d_in[5];
    const float* ln_b    = (const float*)d_in[6];
    const float* Wc      = (const float*)d_in[7];
    const float* Wout    = (const float*)d_in[8];
    float* out = (float*)d_out;

    cudaFuncSetAttribute(tgemm_ca<128>, cudaFuncAttributeMaxDynamicSharedMemorySize, SMEM128);
    cudaFuncSetAttribute(tgemm_ca<64>,  cudaFuncAttributeMaxDynamicSharedMemorySize, SMEM64);

    float *pq, *pk, *psim, *pu, *pop, *py, *pGp, *pG32;
    float *pc32, *px32, *pWq, *pWk, *pWv, *pWo, *pWvT;
    cudaGetSymbolAddress((void**)&pq,   g_q);
    cudaGetSymbolAddress((void**)&pk,   g_k);
    cudaGetSymbolAddress((void**)&psim, g_sim);
    cudaGetSymbolAddress((void**)&pu,   g_u);
    cudaGetSymbolAddress((void**)&pop,  g_op);
    cudaGetSymbolAddress((void**)&py,   g_y);
    cudaGetSymbolAddress((void**)&pGp,  g_Gp);
    cudaGetSymbolAddress((void**)&pG32, g_G32);
    cudaGetSymbolAddress((void**)&pc32, g_ctx32);
    cudaGetSymbolAddress((void**)&px32, g_x32);
    cudaGetSymbolAddress((void**)&pWq,  g_Wq32);
    cudaGetSymbolAddress((void**)&pWk,  g_Wk32);
    cudaGetSymbolAddress((void**)&pWv,  g_Wv32);
    cudaGetSymbolAddress((void**)&pWo,  g_Wo32);
    cudaGetSymbolAddress((void**)&pWvT, g_Wv1T);

    // ---- prepass: rounding, transpose, rowsum ----
    cvt_tf32<<<(BB * NN * DD) / 1024, 256>>>(context, pc32);
    cvt_tf32<<<(BB * NQ * DD) / 1024, 256>>>(x, px32);
    cvt_tf32_3<<<dim3((DD * DD) / 1024, 3), 256>>>(Wk, pWk, Wq, pWq, Wout, pWo);
    cvt_tf32<<<(DD * QR) / 1024, 256>>>(Wv1, pWv);
    trans_round<<<dim3(QR / 32, DD / 32), 256>>>(Wv1);
    rowsum<<<DD / 8, 256>>>(Wv1);

    // ---- G = Wv1 @ Wv1^T, split-K (z = 4 chunks of 1024) ----
    tgemm_ca<128><<<dim3(DD / 128, DD / 128, 4), 256, SMEM128>>>(
        pWv, pWvT, pGp, DD, 1024, QR, DD, DD,
        (size_t)1024, (size_t)1024 * DD, (size_t)DD * DD);
    reduce4<<<(DD * DD) / 1024, 256>>>();

    // ---- y = ctx @ G ----
    tgemm_ca<128><<<dim3(DD / 128, (BB * NN) / 128), 256, SMEM128>>>(
        pc32, pG32, py, DD, DD, DD, DD, DD, 0, 0, 0);
    // ---- LN stats from dots ----
    stats<<<(BB * NN) / 8, 256>>>(context);

    // ---- k, q ----
    tgemm_ca<128><<<dim3(DD / 128, (BB * NN) / 128), 256, SMEM128>>>(
        pc32, pWk, pk, DD, DD, DD, DD, DD, 0, 0, 0);
    tgemm_ca<64><<<dim3(DD / 128, (BB * NQ) / 64), 256, SMEM64>>>(
        px32, pWq, pq, DD, DD, DD, DD, DD, 0, 0, 0);

    // ---- attention ----
    sim_kernel<<<dim3(NN / 32, HH, BB), 256>>>();
    softmax_w<<<BB * HH * NQ, 256>>>();

    // ---- u[b, h*64+i, :] = sum_j w * ctx   (z = batch) ----
    tgemm_ca<128><<<dim3(DD / 128, (HH * NQ) / 128, BB), 256, SMEM128>>>(
        psim, pc32, pu, DD, NN, NN, DD, DD,
        (size_t)HH * NQ * NN, (size_t)NN * DD, (size_t)HH * NQ * DD);

    // ---- t, conv, out ----
    tfin_kernel<<<NQ, 256>>>(ln_g, ln_b);
    conv_kernel<<<BB * NQ, 256>>>(Wc);
    tgemm_ca<64><<<dim3(DD / 128, (BB * NQ) / 64), 256, SMEM64>>>(
        pop, pWo, out, DD, DD, DD, DD, DD, 0, 0, 0);
}

// round 12
// speedup vs baseline: 1.1239x; 1.1239x over previous
#include <cuda_runtime.h>
#include <math.h>
#include <stdint.h>

#define BB 4
#define NQ 64
#define NN 1024
#define DD 768
#define HH 8
#define DH 96
#define RANK 64
#define QR 4096
#define LN_EPS 1e-5f

// ---------------- scratch (static device allocations; no cudaMalloc) ----------------
__device__ float g_q  [BB*NQ*DD];
__device__ float g_k  [BB*NN*DD];              // 12.6 MB
__device__ float g_sim[(size_t)BB*HH*NQ*NN];   // 8.4 MB (attn, then w = attn*inv)
__device__ float g_mu [BB*NN];
__device__ float g_inv[BB*NN];
__device__ float g_s  [BB*HH*NQ];
__device__ float g_u  [(size_t)BB*HH*NQ*DD];   // 6.3 MB
__device__ float g_t  [BB*NQ*HH*RANK];
__device__ float g_op [BB*NQ*DD];

// tf32-rounded operands
__device__ float g_ctx32[(size_t)BB*NN*DD];    // 12.6 MB
__device__ float g_x32  [BB*NQ*DD];
__device__ float g_Wq32 [DD*DD];
__device__ float g_Wk32 [DD*DD];
__device__ float g_Wv32 [(size_t)DD*QR];       // 12.6 MB (rounded Wv1, [768][4096])
__device__ float g_Wo32 [DD*DD];
__device__ float g_Wv1T [(size_t)QR*DD];       // 12.6 MB (rounded Wv1^T, [4096][768])
__device__ float g_rs   [DD];                  // rowsum of Wv1 (original)
__device__ float g_Gp   [(size_t)4*DD*DD];     // split-K partials of G
__device__ float g_G32  [DD*DD];               // G = Wv1 Wv1^T (tf32-rounded)
__device__ float g_y    [(size_t)BB*NN*DD];    // 12.6 MB  y = ctx @ G

// ---------------- helpers ----------------
__device__ __forceinline__ uint32_t s2u(const void* p) {
    return (uint32_t)__cvta_generic_to_shared(p);
}
__device__ __forceinline__ float to_tf32(float x) {
    uint32_t u;
    asm("cvt.rna.tf32.f32 %0, %1;" : "=r"(u) : "f"(x));
    return __uint_as_float(u);
}
__device__ __forceinline__ void cp16(uint32_t dst, const void* src) {
    asm volatile("cp.async.cg.shared.global [%0], [%1], 16;" :: "r"(dst), "l"(src) : "memory");
}
__device__ __forceinline__ void mma_tf32(float* d, const uint32_t* a, const uint32_t* b) {
    asm volatile("mma.sync.aligned.m16n8k8.row.col.f32.tf32.tf32.f32 "
                 "{%0,%1,%2,%3}, {%4,%5,%6,%7}, {%8,%9}, {%0,%1,%2,%3};"
                 : "+f"(d[0]), "+f"(d[1]), "+f"(d[2]), "+f"(d[3])
                 : "r"(a[0]), "r"(a[1]), "r"(a[2]), "r"(a[3]),
                   "r"(b[0]), "r"(b[1]));
}

// ======== 512-thread BM=128 tf32 GEMM: 16 warps (4x4), warp tile 32x32, 3-stage ======
// C[M][Nn] = A[M][K] @ B[K][Nn]; inputs pre-rounded to tf32. M%128==0, Nn%128==0, K%32==0.
#define ASZ128 (128 * 36)
#define BSZ128 (32 * 136)
#define STG128 (ASZ128 + BSZ128)

__global__ void __launch_bounds__(512) tgemm512(const float* __restrict__ A,
                                                const float* __restrict__ Bm,
                                                float* __restrict__ C,
                                                int Nn, int K, int lda, int ldb, int ldc,
                                                size_t sA, size_t sB, size_t sC)
{
    extern __shared__ float sm[];

    A  += blockIdx.z * sA;
    Bm += blockIdx.z * sB;
    C  += blockIdx.z * sC;

    int tid = threadIdx.x;
    int warp = tid >> 5, lane = tid & 31;
    int g = lane >> 2, tg = lane & 3;
    int wm = (warp >> 2) * 32;          // warp row (0,32,64,96)
    int wn = (warp & 3) * 32;           // warp col (0,32,64,96)
    int m0 = blockIdx.y * 128, n0 = blockIdx.x * 128;

    float acc[2][4][4];
    #pragma unroll
    for (int mi = 0; mi < 2; mi++)
        #pragma unroll
        for (int ni = 0; ni < 4; ni++)
            #pragma unroll
            for (int c = 0; c < 4; c++) acc[mi][ni][c] = 0.f;

    int nk = K >> 5;

    auto fill = [&](int stage, int kt) {
        uint32_t asb = s2u(sm + stage * STG128);
        uint32_t bsb = asb + ASZ128 * 4;
        #pragma unroll
        for (int l = 0; l < 2; l++) {
            int seg = tid + l * 512;            // 0..1023
            int row = seg >> 3, sc = seg & 7;
            cp16(asb + (uint32_t)(row * 144 + sc * 16),
                 A + (size_t)(m0 + row) * lda + kt + sc * 4);
        }
        #pragma unroll
        for (int l = 0; l < 2; l++) {
            int seg = tid + l * 512;            // 0..1023
            int row = seg >> 5, sc = seg & 31;
            cp16(bsb + (uint32_t)(row * 544 + sc * 16),
                 Bm + (size_t)(kt + row) * ldb + n0 + sc * 4);
        }
    };

    fill(0, 0);
    asm volatile("cp.async.commit_group;" ::: "memory");
    fill(1, 32);
    asm volatile("cp.async.commit_group;" ::: "memory");

    for (int it = 0; it < nk; it++) {
        asm volatile("cp.async.wait_group 1;" ::: "memory");
        __syncthreads();
        int s = it % 3;
        const float* As = sm + s * STG128;
        const float* Bs = As + ASZ128;

        #pragma unroll
        for (int ks = 0; ks < 4; ks++) {
            int kk = ks * 8;
            uint32_t af[2][4], bf[4][2];
            #pragma unroll
            for (int mi = 0; mi < 2; mi++) {
                int mr = wm + mi * 16 + g;
                af[mi][0] = __float_as_uint(As[ mr      * 36 + kk + tg    ]);
                af[mi][1] = __float_as_uint(As[(mr + 8) * 36 + kk + tg    ]);
                af[mi][2] = __float_as_uint(As[ mr      * 36 + kk + tg + 4]);
                af[mi][3] = __float_as_uint(As[(mr + 8) * 36 + kk + tg + 4]);
            }
            #pragma unroll
            for (int ni = 0; ni < 4; ni++) {
                int nc = wn + ni * 8 + g;
                bf[ni][0] = __float_as_uint(Bs[(kk + tg    ) * 136 + nc]);
                bf[ni][1] = __float_as_uint(Bs[(kk + tg + 4) * 136 + nc]);
            }
            #pragma unroll
            for (int mi = 0; mi < 2; mi++)
                #pragma unroll
                for (int ni = 0; ni < 4; ni++)
                    mma_tf32(acc[mi][ni], af[mi], bf[ni]);
        }

        if (it + 2 < nk) fill((it + 2) % 3, (it + 2) * 32);
        asm volatile("cp.async.commit_group;" ::: "memory");
    }

    #pragma unroll
    for (int mi = 0; mi < 2; mi++) {
        int r0 = m0 + wm + mi * 16 + g;
        #pragma unroll
        for (int ni = 0; ni < 4; ni++) {
            int c = n0 + wn + ni * 8 + 2 * tg;
            *(float2*)(C + (size_t)r0 * ldc + c)       = make_float2(acc[mi][ni][0], acc[mi][ni][1]);
            *(float2*)(C + (size_t)(r0 + 8) * ldc + c) = make_float2(acc[mi][ni][2], acc[mi][ni][3]);
        }
    }
}

// ======== 256-thread BM=64 tf32 GEMM (small-M launches), 3-stage — R9 config ========
__global__ void __launch_bounds__(256) tgemm64(const float* __restrict__ A,
                                               const float* __restrict__ Bm,
                                               float* __restrict__ C,
                                               int Nn, int K, int lda, int ldb, int ldc)
{
    constexpr int ASZ = 64 * 36;
    constexpr int BSZ = 32 * 136;
    constexpr int STG = ASZ + BSZ;

    extern __shared__ float sm[];

    int tid = threadIdx.x;
    int warp = tid >> 5, lane = tid & 31;
    int g = lane >> 2, tg = lane & 3;
    int wm = (warp / 4) * 32;           // 2 warp rows
    int wn = (warp % 4) * 32;           // 4 warp cols
    int m0 = blockIdx.y * 64, n0 = blockIdx.x * 128;

    float acc[2][4][4];
    #pragma unroll
    for (int mi = 0; mi < 2; mi++)
        #pragma unroll
        for (int ni = 0; ni < 4; ni++)
            #pragma unroll
            for (int c = 0; c < 4; c++) acc[mi][ni][c] = 0.f;

    int nk = K >> 5;

    auto fill = [&](int stage, int kt) {
        uint32_t asb = s2u(sm + stage * STG);
        uint32_t bsb = asb + ASZ * 4;
        #pragma unroll
        for (int l = 0; l < 2; l++) {
            int seg = tid + l * 256;
            int row = seg >> 3, sc = seg & 7;
            cp16(asb + (uint32_t)(row * 144 + sc * 16),
                 A + (size_t)(m0 + row) * lda + kt + sc * 4);
        }
        #pragma unroll
        for (int l = 0; l < 4; l++) {
            int seg = tid + l * 256;
            int row = seg >> 5, sc = seg & 31;
            cp16(bsb + (uint32_t)(row * 544 + sc * 16),
                 Bm + (size_t)(kt + row) * ldb + n0 + sc * 4);
        }
    };

    fill(0, 0);
    asm volatile("cp.async.commit_group;" ::: "memory");
    fill(1, 32);
    asm volatile("cp.async.commit_group;" ::: "memory");

    for (int it = 0; it < nk; it++) {
        asm volatile("cp.async.wait_group 1;" ::: "memory");
        __syncthreads();
        int s = it % 3;
        const float* As = sm + s * STG;
        const float* Bs = As + ASZ;

        #pragma unroll
        for (int ks = 0; ks < 4; ks++) {
            int kk = ks * 8;
            uint32_t af[2][4], bf[4][2];
            #pragma unroll
            for (int mi = 0; mi < 2; mi++) {
                int mr = wm + mi * 16 + g;
                af[mi][0] = __float_as_uint(As[ mr      * 36 + kk + tg    ]);
                af[mi][1] = __float_as_uint(As[(mr + 8) * 36 + kk + tg    ]);
                af[mi][2] = __float_as_uint(As[ mr      * 36 + kk + tg + 4]);
                af[mi][3] = __float_as_uint(As[(mr + 8) * 36 + kk + tg + 4]);
            }
            #pragma unroll
            for (int ni = 0; ni < 4; ni++) {
                int nc = wn + ni * 8 + g;
                bf[ni][0] = __float_as_uint(Bs[(kk + tg    ) * 136 + nc]);
                bf[ni][1] = __float_as_uint(Bs[(kk + tg + 4) * 136 + nc]);
            }
            #pragma unroll
            for (int mi = 0; mi < 2; mi++)
                #pragma unroll
                for (int ni = 0; ni < 4; ni++)
                    mma_tf32(acc[mi][ni], af[mi], bf[ni]);
        }

        if (it + 2 < nk) fill((it + 2) % 3, (it + 2) * 32);
        asm volatile("cp.async.commit_group;" ::: "memory");
    }

    #pragma unroll
    for (int mi = 0; mi < 2; mi++) {
        int r0 = m0 + wm + mi * 16 + g;
        #pragma unroll
        for (int ni = 0; ni < 4; ni++) {
            int c = n0 + wn + ni * 8 + 2 * tg;
            *(float2*)(C + (size_t)r0 * ldc + c)       = make_float2(acc[mi][ni][0], acc[mi][ni][1]);
            *(float2*)(C + (size_t)(r0 + 8) * ldc + c) = make_float2(acc[mi][ni][2], acc[mi][ni][3]);
        }
    }
}

// ---------------- tf32 rounding prepass ----------------
__global__ __launch_bounds__(256) void cvt_tf32(const float* __restrict__ in,
                                                float* __restrict__ outp)
{
    size_t i = (size_t)blockIdx.x * 256 + threadIdx.x;
    float4 v = ((const float4*)in)[i];
    v.x = to_tf32(v.x); v.y = to_tf32(v.y);
    v.z = to_tf32(v.z); v.w = to_tf32(v.w);
    ((float4*)outp)[i] = v;
}

// three 768x768 weights in one launch (y selects)
__global__ __launch_bounds__(256) void cvt_tf32_3(const float* __restrict__ i0, float* o0,
                                                  const float* __restrict__ i1, float* o1,
                                                  const float* __restrict__ i2, float* o2)
{
    const float* in = (blockIdx.y == 0) ? i0 : (blockIdx.y == 1) ? i1 : i2;
    float* outp     = (blockIdx.y == 0) ? o0 : (blockIdx.y == 1) ? o1 : o2;
    size_t i = (size_t)blockIdx.x * 256 + threadIdx.x;
    float4 v = ((const float4*)in)[i];
    v.x = to_tf32(v.x); v.y = to_tf32(v.y);
    v.z = to_tf32(v.z); v.w = to_tf32(v.w);
    ((float4*)outp)[i] = v;
}

// ---------------- Wv1 [768][4096] -> Wv1T [4096][768] (tf32-rounded) ----------------
__global__ __launch_bounds__(256) void trans_round(const float* __restrict__ W)
{
    __shared__ float tile[32][33];
    int c0 = blockIdx.x * 32, d0 = blockIdx.y * 32;
    int tid = threadIdx.x;
    int r = tid >> 5, cl = tid & 31;
    #pragma unroll
    for (int p = 0; p < 4; p++)
        tile[r + p * 8][cl] = W[(size_t)(d0 + r + p * 8) * QR + c0 + cl];
    __syncthreads();
    #pragma unroll
    for (int p = 0; p < 4; p++)
        g_Wv1T[(size_t)(c0 + r + p * 8) * DD + d0 + cl] = to_tf32(tile[cl][r + p * 8]);
}

// ---------------- rs[d] = sum_c Wv1[d][c]  (warp per row) ----------------
__global__ __launch_bounds__(256) void rowsum(const float* __restrict__ W)
{
    int row = blockIdx.x * 8 + (threadIdx.x >> 5);
    int lane = threadIdx.x & 31;
    const float* p = W + (size_t)row * QR;
    float s = 0.f;
    for (int c = lane; c < QR; c += 32) s += p[c];
    #pragma unroll
    for (int o = 16; o > 0; o >>= 1) s += __shfl_xor_sync(0xFFFFFFFF, s, o);
    if (lane == 0) g_rs[row] = s;
}

// ---------------- G = sum of 4 split-K partials, tf32-rounded ----------------
__global__ __launch_bounds__(256) void reduce4()
{
    size_t i = (size_t)blockIdx.x * 256 + threadIdx.x;
    const float4* P = (const float4*)g_Gp;
    size_t st = (size_t)DD * DD / 4;
    float4 a = P[i], b = P[i + st], c = P[i + 2 * st], d = P[i + 3 * st];
    float4 o;
    o.x = to_tf32(a.x + b.x + c.x + d.x);
    o.y = to_tf32(a.y + b.y + c.y + d.y);
    o.z = to_tf32(a.z + b.z + c.z + d.z);
    o.w = to_tf32(a.w + b.w + c.w + d.w);
    ((float4*)g_G32)[i] = o;
}

// ---------------- stats: mu_j = ctx_j . rs / 4096 ; inv_j from ctx_j . y_j ----------
__global__ __launch_bounds__(256) void stats(const float* __restrict__ ctx)
{
    int row  = blockIdx.x * 8 + (threadIdx.x >> 5);
    int lane = threadIdx.x & 31;
    const float* cr = ctx + (size_t)row * DD;
    const float* yr = g_y + (size_t)row * DD;
    float md = 0.f, ed = 0.f;
    for (int d = lane; d < DD; d += 32) {
        float c = cr[d];
        md += c * g_rs[d];
        ed += c * yr[d];
    }
    #pragma unroll
    for (int o = 16; o > 0; o >>= 1) {
        md += __shfl_xor_sync(0xFFFFFFFF, md, o);
        ed += __shfl_xor_sync(0xFFFFFFFF, ed, o);
    }
    if (lane == 0) {
        float mu = md * (1.0f / QR);
        float e2 = ed * (1.0f / QR);
        g_mu[row]  = mu;
        g_inv[row] = rsqrtf(e2 - mu * mu + LN_EPS);
    }
}

// ---------------- sim[b,h,i,j] = (1/sqrt(dh)) q.k ----------------
__global__ __launch_bounds__(256) void sim_kernel()
{
    __shared__ float qs[64][97];
    __shared__ float ks[32][97];
    int jt = blockIdx.x, h = blockIdx.y, b = blockIdx.z;
    int tid = threadIdx.x;

    for (int idx = tid; idx < 64 * 96; idx += 256) {
        int i = idx / 96, c = idx % 96;
        qs[i][c] = g_q[(size_t)(b * NQ + i) * DD + h * DH + c];
    }
    for (int idx = tid; idx < 32 * 96; idx += 256) {
        int j = idx / 96, c = idx % 96;
        ks[j][c] = g_k[(size_t)(b * NN + jt * 32 + j) * DD + h * DH + c];
    }
    __syncthreads();

    int tx = tid & 15, ty = tid >> 4;
    float acc[4][2];
    #pragma unroll
    for (int ii = 0; ii < 4; ii++) { acc[ii][0] = 0.f; acc[ii][1] = 0.f; }

    #pragma unroll 4
    for (int c = 0; c < 96; c++) {
        float qv[4], kv[2];
        #pragma unroll
        for (int ii = 0; ii < 4; ii++) qv[ii] = qs[ty * 4 + ii][c];
        kv[0] = ks[tx * 2][c];
        kv[1] = ks[tx * 2 + 1][c];
        #pragma unroll
        for (int ii = 0; ii < 4; ii++) {
            acc[ii][0] = fmaf(qv[ii], kv[0], acc[ii][0]);
            acc[ii][1] = fmaf(qv[ii], kv[1], acc[ii][1]);
        }
    }

    const float sc = 0.10206207261596577f;
    #pragma unroll
    for (int ii = 0; ii < 4; ii++)
        #pragma unroll
        for (int jj = 0; jj < 2; jj++) {
            int i = ty * 4 + ii, j = jt * 32 + tx * 2 + jj;
            g_sim[((size_t)(b * HH + h) * NQ + i) * NN + j] = acc[ii][jj] * sc;
        }
}

// -------- softmax + fold: w = tf32(attn*inv_j) in place; s[row] = sum attn*inv*mu ---
__global__ __launch_bounds__(256) void softmax_w()
{
    int row = blockIdx.x;          // (b*8+h)*64+i
    int b = row >> 9;
    float4* p = (float4*)(g_sim + (size_t)row * NN);
    __shared__ float red[256];
    int tid = threadIdx.x;

    float4 v = p[tid];
    float m = fmaxf(fmaxf(v.x, v.y), fmaxf(v.z, v.w));
    red[tid] = m; __syncthreads();
    for (int o = 128; o > 0; o >>= 1) {
        if (tid < o) red[tid] = fmaxf(red[tid], red[tid + o]);
        __syncthreads();
    }
    m = red[0]; __syncthreads();

    v.x = __expf(v.x - m); v.y = __expf(v.y - m);
    v.z = __expf(v.z - m); v.w = __expf(v.w - m);
    red[tid] = v.x + v.y + v.z + v.w; __syncthreads();
    for (int o = 128; o > 0; o >>= 1) {
        if (tid < o) red[tid] += red[tid + o];
        __syncthreads();
    }
    float invs = 1.0f / red[0];
    __syncthreads();

    float4 mu4 = ((const float4*)(g_mu  + b * NN))[tid];
    float4 iv4 = ((const float4*)(g_inv + b * NN))[tid];
    float4 w;
    w.x = v.x * invs * iv4.x; w.y = v.y * invs * iv4.y;
    w.z = v.z * invs * iv4.z; w.w = v.w * invs * iv4.w;
    float sacc = w.x * mu4.x + w.y * mu4.y + w.z * mu4.z + w.w * mu4.w;
    w.x = to_tf32(w.x); w.y = to_tf32(w.y);
    w.z = to_tf32(w.z); w.w = to_tf32(w.w);
    p[tid] = w;

    red[tid] = sacc; __syncthreads();
    for (int o = 128; o > 0; o >>= 1) {
        if (tid < o) red[tid] += red[tid + o];
        __syncthreads();
    }
    if (tid == 0) g_s[row] = red[0];
}

// ---- t[b,i,h,r] = gam[ir]*( sum_d u[b,h,i,d]*Wv1T[ir][d] - s[b,h,i] ) + bet[ir] ----
__global__ __launch_bounds__(256) void tfin_kernel(const float* __restrict__ gam,
                                                   const float* __restrict__ bet)
{
    int b = blockIdx.x >> 6, i = blockIdx.x & 63;
    __shared__ float u_s[HH][DD];    // 24 KB
    int tid = threadIdx.x;
    int warp = tid >> 5, lane = tid & 31;

    for (int idx = tid; idx < HH * DD; idx += 256) {
        int h = idx / DD, d = idx % DD;
        u_s[h][d] = g_u[((size_t)b * 512 + h * 64 + i) * DD + d];
    }
    __syncthreads();

    #pragma unroll
    for (int rr = 0; rr < 8; rr++) {
        int r = warp * 8 + rr;
        const float* wv = g_Wv1T + (size_t)(i * RANK + r) * DD;
        float a[8];
        #pragma unroll
        for (int h = 0; h < 8; h++) a[h] = 0.f;
        for (int d = lane; d < DD; d += 32) {
            float wvv = wv[d];
            #pragma unroll
            for (int h = 0; h < 8; h++) a[h] = fmaf(u_s[h][d], wvv, a[h]);
        }
        #pragma unroll
        for (int o = 16; o > 0; o >>= 1)
            #pragma unroll
            for (int h = 0; h < 8; h++) a[h] += __shfl_xor_sync(0xFFFFFFFF, a[h], o);
        if (lane == 0) {
            float gm = gam[i * RANK + r], bt = bet[i * RANK + r];
            #pragma unroll
            for (int h = 0; h < 8; h++) {
                float sv = g_s[(b * HH + h) * NQ + i];
                g_t[((size_t)(b * NQ + i) * HH + h) * RANK + r] = gm * (a[h] - sv) + bt;
            }
        }
    }
}

// ---- out_pre[b,i,d] = sum_r t[b,i,head(d),r]*Wc[i,r,d]  (tf32-rounded write) ------
__global__ __launch_bounds__(256) void conv_kernel(const float* __restrict__ Wc)
{
    int b = blockIdx.x >> 6, i = blockIdx.x & 63;
    __shared__ float ts[HH * RANK];
    int tid = threadIdx.x;
    for (int idx = tid; idx < HH * RANK; idx += 256)
        ts[idx] = g_t[(size_t)(b * NQ + i) * (HH * RANK) + idx];
    __syncthreads();

    for (int dd = tid; dd < DD; dd += 256) {
        int h = dd / DH;
        float acc = 0.f;
        const float* wp = Wc + (size_t)i * RANK * DD + dd;
        #pragma unroll 8
        for (int rr = 0; rr < RANK; rr++)
            acc = fmaf(ts[h * RANK + rr], wp[(size_t)rr * DD], acc);
        g_op[(size_t)(b * NQ + i) * DD + dd] = to_tf32(acc);
    }
}

// ---------------- launch ----------------
#define SMEM128 (3 * STG128 * 4)                  // 107520
#define SMEM64  (3 * (64 * 36 + 32 * 136) * 4)    //  79872

extern "C" void kernel_launch(void* const* d_in, const int* in_sizes, int n_in,
                              void* d_out, int out_size)
{
    const float* x       = (const float*)d_in[0];
    const float* context = (const float*)d_in[1];
    const float* Wq      = (const float*)d_in[2];
    const float* Wk      = (const float*)d_in[3];
    const float* Wv1     = (const float*)d_in[4];
    const float* ln_g    = (const float*)d_in[5];
    const float* ln_b    = (const float*)d_in[6];
    const float* Wc      = (const float*)d_in[7];
    const float* Wout    = (const float*)d_in[8];
    float* out = (float*)d_out;

    cudaFuncSetAttribute(tgemm512, cudaFuncAttributeMaxDynamicSharedMemorySize, SMEM128);
    cudaFuncSetAttribute(tgemm64,  cudaFuncAttributeMaxDynamicSharedMemorySize, SMEM64);

    float *pq, *pk, *psim, *pu, *pop, *py, *pGp, *pG32;
    float *pc32, *px32, *pWq, *pWk, *pWv, *pWo, *pWvT;
    cudaGetSymbolAddress((void**)&pq,   g_q);
    cudaGetSymbolAddress((void**)&pk,   g_k);
    cudaGetSymbolAddress((void**)&psim, g_sim);
    cudaGetSymbolAddress((void**)&pu,   g_u);
    cudaGetSymbolAddress((void**)&pop,  g_op);
    cudaGetSymbolAddress((void**)&py,   g_y);
    cudaGetSymbolAddress((void**)&pGp,  g_Gp);
    cudaGetSymbolAddress((void**)&pG32, g_G32);
    cudaGetSymbolAddress((void**)&pc32, g_ctx32);
    cudaGetSymbolAddress((void**)&px32, g_x32);
    cudaGetSymbolAddress((void**)&pWq,  g_Wq32);
    cudaGetSymbolAddress((void**)&pWk,  g_Wk32);
    cudaGetSymbolAddress((void**)&pWv,  g_Wv32);
    cudaGetSymbolAddress((void**)&pWo,  g_Wo32);
    cudaGetSymbolAddress((void**)&pWvT, g_Wv1T);

    // ---- prepass: rounding, transpose, rowsum ----
    cvt_tf32<<<(BB * NN * DD) / 1024, 256>>>(context, pc32);
    cvt_tf32<<<(BB * NQ * DD) / 1024, 256>>>(x, px32);
    cvt_tf32_3<<<dim3((DD * DD) / 1024, 3), 256>>>(Wk, pWk, Wq, pWq, Wout, pWo);
    cvt_tf32<<<(DD * QR) / 1024, 256>>>(Wv1, pWv);
    trans_round<<<dim3(QR / 32, DD / 32), 256>>>(Wv1);
    rowsum<<<DD / 8, 256>>>(Wv1);

    // ---- G = Wv1 @ Wv1^T, split-K (z = 4 chunks of 1024) ----
    tgemm512<<<dim3(DD / 128, DD / 128, 4), 512, SMEM128>>>(
        pWv, pWvT, pGp, DD, 1024, QR, DD, DD,
        (size_t)1024, (size_t)1024 * DD, (size_t)DD * DD);
    reduce4<<<(DD * DD) / 1024, 256>>>();

    // ---- y = ctx @ G ----
    tgemm512<<<dim3(DD / 128, (BB * NN) / 128), 512, SMEM128>>>(
        pc32, pG32, py, DD, DD, DD, DD, DD, 0, 0, 0);
    // ---- LN stats from dots ----
    stats<<<(BB * NN) / 8, 256>>>(context);

    // ---- k, q ----
    tgemm512<<<dim3(DD / 128, (BB * NN) / 128), 512, SMEM128>>>(
        pc32, pWk, pk, DD, DD, DD, DD, DD, 0, 0, 0);
    tgemm64<<<dim3(DD / 128, (BB * NQ) / 64), 256, SMEM64>>>(
        px32, pWq, pq, DD, DD, DD, DD, DD);

    // ---- attention ----
    sim_kernel<<<dim3(NN / 32, HH, BB), 256>>>();
    softmax_w<<<BB * HH * NQ, 256>>>();

    // ---- u[b, h*64+i, :] = sum_j w * ctx   (z = batch) ----
    tgemm512<<<dim3(DD / 128, (HH * NQ) / 128, BB), 512, SMEM128>>>(
        psim, pc32, pu, DD, NN, NN, DD, DD,
        (size_t)HH * NQ * NN, (size_t)NN * DD, (size_t)HH * NQ * DD);

    // ---- t, conv, out ----
    tfin_kernel<<<BB * NQ, 256>>>(ln_g, ln_b);
    conv_kernel<<<BB * NQ, 256>>>(Wc);
    tgemm64<<<dim3(DD / 128, (BB * NQ) / 64), 256, SMEM64>>>(
        pop, pWo, out, DD, DD, DD, DD, DD);
}

// round 13
// speedup vs baseline: 1.3260x; 1.1798x over previous
#include <cuda_runtime.h>
#include <math.h>
#include <stdint.h>

#define BB 4
#define NQ 64
#define NN 1024
#define DD 768
#define HH 8
#define DH 96
#define RANK 64
#define QR 4096
#define LN_EPS 1e-5f

// ---------------- scratch (static device allocations; no cudaMalloc) ----------------
__device__ float g_q  [BB*NQ*DD];
__device__ float g_k  [BB*NN*DD];              // 12.6 MB
__device__ float g_sim[(size_t)BB*HH*NQ*NN];   // 8.4 MB (logits, then w = attn*inv)
__device__ float g_mu [BB*NN];
__device__ float g_inv[BB*NN];
__device__ float g_s  [BB*HH*NQ];
__device__ float g_u  [(size_t)BB*HH*NQ*DD];   // 6.3 MB
__device__ float g_t  [BB*NQ*HH*RANK];
__device__ float g_op [BB*NQ*DD];

// tf32-rounded operands
__device__ float g_ctx32[(size_t)BB*NN*DD];    // 12.6 MB
__device__ float g_x32  [BB*NQ*DD];
__device__ float g_Wq32 [DD*DD];
__device__ float g_Wk32 [DD*DD];
__device__ float g_Wv32 [(size_t)DD*QR];       // 12.6 MB (rounded Wv1, [768][4096])
__device__ float g_Wo32 [DD*DD];
__device__ float g_Wv1T [(size_t)QR*DD];       // 12.6 MB (rounded Wv1^T, [4096][768])
__device__ float g_rs   [DD];                  // rowsum of Wv1 (original)
__device__ float g_Gp   [(size_t)4*DD*DD];     // split-K partials of G
__device__ float g_G32  [DD*DD];               // G = Wv1 Wv1^T (tf32-rounded)
__device__ float g_y    [(size_t)BB*NN*DD];    // 12.6 MB  y = ctx @ G

// ---------------- helpers ----------------
__device__ __forceinline__ uint32_t s2u(const void* p) {
    return (uint32_t)__cvta_generic_to_shared(p);
}
__device__ __forceinline__ float to_tf32(float x) {
    uint32_t u;
    asm("cvt.rna.tf32.f32 %0, %1;" : "=r"(u) : "f"(x));
    return __uint_as_float(u);
}
__device__ __forceinline__ void cp16(uint32_t dst, const void* src) {
    asm volatile("cp.async.cg.shared.global [%0], [%1], 16;" :: "r"(dst), "l"(src) : "memory");
}
__device__ __forceinline__ void mma_tf32(float* d, const uint32_t* a, const uint32_t* b) {
    asm volatile("mma.sync.aligned.m16n8k8.row.col.f32.tf32.tf32.f32 "
                 "{%0,%1,%2,%3}, {%4,%5,%6,%7}, {%8,%9}, {%0,%1,%2,%3};"
                 : "+f"(d[0]), "+f"(d[1]), "+f"(d[2]), "+f"(d[3])
                 : "r"(a[0]), "r"(a[1]), "r"(a[2]), "r"(a[3]),
                   "r"(b[0]), "r"(b[1]));
}

// ---------------- tf32 GEMM, cp.async 3-stage, z-batched — R9 config (FROZEN) -------
template<int BM>
__global__ void __launch_bounds__(256) tgemm_ca(const float* __restrict__ A,
                                                const float* __restrict__ Bm,
                                                float* __restrict__ C,
                                                int Nn, int K, int lda, int ldb, int ldc,
                                                size_t sA, size_t sB, size_t sC)
{
    constexpr int WCOLS = (BM == 128) ? 2 : 4;
    constexpr int WN    = 128 / WCOLS;
    constexpr int NI    = WN / 8;
    constexpr int ASZ   = BM * 36;
    constexpr int BSZ   = 32 * 136;
    constexpr int STG   = ASZ + BSZ;
    constexpr int ALD   = BM * 8 / 256;

    extern __shared__ float sm[];

    A  += blockIdx.z * sA;
    Bm += blockIdx.z * sB;
    C  += blockIdx.z * sC;

    int tid = threadIdx.x;
    int warp = tid >> 5, lane = tid & 31;
    int g = lane >> 2, tg = lane & 3;
    int wm = (warp / WCOLS) * 32;
    int wn = (warp % WCOLS) * WN;
    int m0 = blockIdx.y * BM, n0 = blockIdx.x * 128;

    float acc[2][NI][4];
    #pragma unroll
    for (int mi = 0; mi < 2; mi++)
        #pragma unroll
        for (int ni = 0; ni < NI; ni++)
            #pragma unroll
            for (int c = 0; c < 4; c++) acc[mi][ni][c] = 0.f;

    int nk = K >> 5;

    auto fill = [&](int stage, int kt) {
        uint32_t asb = s2u(sm + stage * STG);
        uint32_t bsb = asb + ASZ * 4;
        #pragma unroll
        for (int l = 0; l < ALD; l++) {
            int seg = tid + l * 256;
            int row = seg >> 3, sc = seg & 7;
            cp16(asb + (uint32_t)(row * 144 + sc * 16),
                 A + (size_t)(m0 + row) * lda + kt + sc * 4);
        }
        #pragma unroll
        for (int l = 0; l < 4; l++) {
            int seg = tid + l * 256;
            int row = seg >> 5, sc = seg & 31;
            cp16(bsb + (uint32_t)(row * 544 + sc * 16),
                 Bm + (size_t)(kt + row) * ldb + n0 + sc * 4);
        }
    };

    fill(0, 0);
    asm volatile("cp.async.commit_group;" ::: "memory");
    fill(1, 32);
    asm volatile("cp.async.commit_group;" ::: "memory");

    for (int it = 0; it < nk; it++) {
        asm volatile("cp.async.wait_group 1;" ::: "memory");
        __syncthreads();
        int s = it % 3;
        const float* As = sm + s * STG;
        const float* Bs = As + ASZ;

        #pragma unroll
        for (int ks = 0; ks < 4; ks++) {
            int kk = ks * 8;
            uint32_t af[2][4], bf[NI][2];
            #pragma unroll
            for (int mi = 0; mi < 2; mi++) {
                int mr = wm + mi * 16 + g;
                af[mi][0] = __float_as_uint(As[ mr      * 36 + kk + tg    ]);
                af[mi][1] = __float_as_uint(As[(mr + 8) * 36 + kk + tg    ]);
                af[mi][2] = __float_as_uint(As[ mr      * 36 + kk + tg + 4]);
                af[mi][3] = __float_as_uint(As[(mr + 8) * 36 + kk + tg + 4]);
            }
            #pragma unroll
            for (int ni = 0; ni < NI; ni++) {
                int nc = wn + ni * 8 + g;
                bf[ni][0] = __float_as_uint(Bs[(kk + tg    ) * 136 + nc]);
                bf[ni][1] = __float_as_uint(Bs[(kk + tg + 4) * 136 + nc]);
            }
            #pragma unroll
            for (int mi = 0; mi < 2; mi++)
                #pragma unroll
                for (int ni = 0; ni < NI; ni++)
                    mma_tf32(acc[mi][ni], af[mi], bf[ni]);
        }

        if (it + 2 < nk) fill((it + 2) % 3, (it + 2) * 32);
        asm volatile("cp.async.commit_group;" ::: "memory");
    }

    #pragma unroll
    for (int mi = 0; mi < 2; mi++) {
        int r0 = m0 + wm + mi * 16 + g;
        #pragma unroll
        for (int ni = 0; ni < NI; ni++) {
            int c = n0 + wn + ni * 8 + 2 * tg;
            *(float2*)(C + (size_t)r0 * ldc + c)       = make_float2(acc[mi][ni][0], acc[mi][ni][1]);
            *(float2*)(C + (size_t)(r0 + 8) * ldc + c) = make_float2(acc[mi][ni][2], acc[mi][ni][3]);
        }
    }
}

// ======== sim GEMM: logits[b,h] = (q_head @ k_head^T) * 96^-0.5 via mma.sync ========
// z = b*8+h. A = q rows i (lda=768, head col offset). B = k rows j (K-major memory):
// B tile stored n-major in smem Bs2[128][40] with xor-4 swizzle -> conflict-free.
// M=64, N=1024 (tiles of 128), K=96 (3 k-chunks). 256 thr, 8 warps (2x4), 3-stage.
#define SIM_ASZ (64 * 36)
#define SIM_BSZ (128 * 40)
#define SIM_STG (SIM_ASZ + SIM_BSZ)
#define SIM_SMEM (3 * SIM_STG * 4)

__global__ void __launch_bounds__(256) simgemm()
{
    extern __shared__ float sm[];

    int z = blockIdx.z;                   // b*8+h
    int b = z >> 3, h = z & 7;
    const float* A = g_q + (size_t)b * NQ * DD + h * DH;
    const float* B = g_k + (size_t)b * NN * DD + h * DH;
    float* C = g_sim + (size_t)z * NQ * NN;

    int tid = threadIdx.x;
    int warp = tid >> 5, lane = tid & 31;
    int g = lane >> 2, tg = lane & 3;
    int wm = (warp / 4) * 32;             // 2 warp rows
    int wn = (warp % 4) * 32;             // 4 warp cols
    int n0 = blockIdx.x * 128;

    float acc[2][4][4];
    #pragma unroll
    for (int mi = 0; mi < 2; mi++)
        #pragma unroll
        for (int ni = 0; ni < 4; ni++)
            #pragma unroll
            for (int c = 0; c < 4; c++) acc[mi][ni][c] = 0.f;

    auto fill = [&](int stage, int kt) {
        uint32_t asb = s2u(sm + stage * SIM_STG);
        uint32_t bsb = asb + SIM_ASZ * 4;
        #pragma unroll
        for (int l = 0; l < 2; l++) {               // A: 64 rows x 8 16B segs
            int seg = tid + l * 256;
            int row = seg >> 3, sc = seg & 7;
            cp16(asb + (uint32_t)(row * 144 + sc * 16),
                 A + (size_t)row * DD + kt + sc * 4);
        }
        #pragma unroll
        for (int l = 0; l < 4; l++) {               // B: 128 rows (n) x 8 16B segs (k)
            int seg = tid + l * 256;
            int row = seg >> 3, sc = seg & 7;
            int scx = sc ^ ((row >> 2) & 1);        // xor-4 float swizzle (16B units)
            cp16(bsb + (uint32_t)(row * 160 + scx * 16),
                 B + (size_t)(n0 + row) * DD + kt + sc * 4);
        }
    };

    fill(0, 0);
    asm volatile("cp.async.commit_group;" ::: "memory");
    fill(1, 32);
    asm volatile("cp.async.commit_group;" ::: "memory");

    for (int it = 0; it < 3; it++) {
        asm volatile("cp.async.wait_group 1;" ::: "memory");
        __syncthreads();
        int s = it;
        const float* As  = sm + s * SIM_STG;
        const float* Bs2 = As + SIM_ASZ;

        #pragma unroll
        for (int ks = 0; ks < 4; ks++) {
            int kk = ks * 8;
            uint32_t af[2][4], bf[4][2];
            #pragma unroll
            for (int mi = 0; mi < 2; mi++) {
                int mr = wm + mi * 16 + g;
                af[mi][0] = __float_as_uint(As[ mr      * 36 + kk + tg    ]);
                af[mi][1] = __float_as_uint(As[(mr + 8) * 36 + kk + tg    ]);
                af[mi][2] = __float_as_uint(As[ mr      * 36 + kk + tg + 4]);
                af[mi][3] = __float_as_uint(As[(mr + 8) * 36 + kk + tg + 4]);
            }
            #pragma unroll
            for (int ni = 0; ni < 4; ni++) {
                int nc = wn + ni * 8 + g;
                int xr = 4 * ((nc >> 2) & 1);
                bf[ni][0] = __float_as_uint(Bs2[nc * 40 + (kk + (tg     ^ xr))]);
                bf[ni][1] = __float_as_uint(Bs2[nc * 40 + (kk + ((tg+4) ^ xr))]);
            }
            #pragma unroll
            for (int mi = 0; mi < 2; mi++)
                #pragma unroll
                for (int ni = 0; ni < 4; ni++)
                    mma_tf32(acc[mi][ni], af[mi], bf[ni]);
        }

        if (it + 2 < 3) fill(it + 2, (it + 2) * 32);
        asm volatile("cp.async.commit_group;" ::: "memory");
    }

    const float sc = 0.10206207261596577f;   // 96^-0.5
    #pragma unroll
    for (int mi = 0; mi < 2; mi++) {
        int r0 = wm + mi * 16 + g;
        #pragma unroll
        for (int ni = 0; ni < 4; ni++) {
            int c = n0 + wn + ni * 8 + 2 * tg;
            *(float2*)(C + (size_t)r0 * NN + c) =
                make_float2(acc[mi][ni][0] * sc, acc[mi][ni][1] * sc);
            *(float2*)(C + (size_t)(r0 + 8) * NN + c) =
                make_float2(acc[mi][ni][2] * sc, acc[mi][ni][3] * sc);
        }
    }
}

// ---------------- merged tf32 rounding prepass (all 6 buffers, one launch) ----------
// segments (blocks of 1024 floats): ctx 3072 | x 192 | Wq 576 | Wo 576 | Wk 576 | Wv1 3072
__global__ __launch_bounds__(256) void cvt_all(const float* __restrict__ ctx,
                                               const float* __restrict__ x,
                                               const float* __restrict__ Wq,
                                               const float* __restrict__ Wo,
                                               const float* __restrict__ Wk,
                                               const float* __restrict__ Wv1)
{
    int bid = blockIdx.x;
    const float* in; float* outp; int lb;
    if      (bid < 3072) { in = ctx; outp = g_ctx32; lb = bid; }
    else if (bid < 3264) { in = x;   outp = g_x32;   lb = bid - 3072; }
    else if (bid < 3840) { in = Wq;  outp = g_Wq32;  lb = bid - 3264; }
    else if (bid < 4416) { in = Wo;  outp = g_Wo32;  lb = bid - 3840; }
    else if (bid < 4992) { in = Wk;  outp = g_Wk32;  lb = bid - 4416; }
    else                 { in = Wv1; outp = g_Wv32;  lb = bid - 4992; }
    size_t i = (size_t)lb * 256 + threadIdx.x;
    float4 v = ((const float4*)in)[i];
    v.x = to_tf32(v.x); v.y = to_tf32(v.y);
    v.z = to_tf32(v.z); v.w = to_tf32(v.w);
    ((float4*)outp)[i] = v;
}

// ---------------- Wv1 [768][4096] -> Wv1T [4096][768] (tf32-rounded) ----------------
__global__ __launch_bounds__(256) void trans_round(const float* __restrict__ W)
{
    __shared__ float tile[32][33];
    int c0 = blockIdx.x * 32, d0 = blockIdx.y * 32;
    int tid = threadIdx.x;
    int r = tid >> 5, cl = tid & 31;
    #pragma unroll
    for (int p = 0; p < 4; p++)
        tile[r + p * 8][cl] = W[(size_t)(d0 + r + p * 8) * QR + c0 + cl];
    __syncthreads();
    #pragma unroll
    for (int p = 0; p < 4; p++)
        g_Wv1T[(size_t)(c0 + r + p * 8) * DD + d0 + cl] = to_tf32(tile[cl][r + p * 8]);
}

// ---------------- rs[d] = sum_c Wv1[d][c]  (warp per row) ----------------
__global__ __launch_bounds__(256) void rowsum(const float* __restrict__ W)
{
    int row = blockIdx.x * 8 + (threadIdx.x >> 5);
    int lane = threadIdx.x & 31;
    const float* p = W + (size_t)row * QR;
    float s = 0.f;
    for (int c = lane; c < QR; c += 32) s += p[c];
    #pragma unroll
    for (int o = 16; o > 0; o >>= 1) s += __shfl_xor_sync(0xFFFFFFFF, s, o);
    if (lane == 0) g_rs[row] = s;
}

// ---------------- G = sum of 4 split-K partials, tf32-rounded ----------------
__global__ __launch_bounds__(256) void reduce4()
{
    size_t i = (size_t)blockIdx.x * 256 + threadIdx.x;
    const float4* P = (const float4*)g_Gp;
    size_t st = (size_t)DD * DD / 4;
    float4 a = P[i], b = P[i + st], c = P[i + 2 * st], d = P[i + 3 * st];
    float4 o;
    o.x = to_tf32(a.x + b.x + c.x + d.x);
    o.y = to_tf32(a.y + b.y + c.y + d.y);
    o.z = to_tf32(a.z + b.z + c.z + d.z);
    o.w = to_tf32(a.w + b.w + c.w + d.w);
    ((float4*)g_G32)[i] = o;
}

// ---------------- stats: mu_j = ctx_j . rs / 4096 ; inv_j from ctx_j . y_j ----------
__global__ __launch_bounds__(256) void stats(const float* __restrict__ ctx)
{
    int row  = blockIdx.x * 8 + (threadIdx.x >> 5);
    int lane = threadIdx.x & 31;
    const float* cr = ctx + (size_t)row * DD;
    const float* yr = g_y + (size_t)row * DD;
    float md = 0.f, ed = 0.f;
    for (int d = lane; d < DD; d += 32) {
        float c = cr[d];
        md += c * g_rs[d];
        ed += c * yr[d];
    }
    #pragma unroll
    for (int o = 16; o > 0; o >>= 1) {
        md += __shfl_xor_sync(0xFFFFFFFF, md, o);
        ed += __shfl_xor_sync(0xFFFFFFFF, ed, o);
    }
    if (lane == 0) {
        float mu = md * (1.0f / QR);
        float e2 = ed * (1.0f / QR);
        g_mu[row]  = mu;
        g_inv[row] = rsqrtf(e2 - mu * mu + LN_EPS);
    }
}

// -------- softmax + fold: w = tf32(attn*inv_j) in place; s[row] = sum attn*inv*mu ---
__global__ __launch_bounds__(256) void softmax_w()
{
    int row = blockIdx.x;          // (b*8+h)*64+i
    int b = row >> 9;
    float4* p = (float4*)(g_sim + (size_t)row * NN);
    __shared__ float red[256];
    int tid = threadIdx.x;

    float4 v = p[tid];
    float m = fmaxf(fmaxf(v.x, v.y), fmaxf(v.z, v.w));
    red[tid] = m; __syncthreads();
    for (int o = 128; o > 0; o >>= 1) {
        if (tid < o) red[tid] = fmaxf(red[tid], red[tid + o]);
        __syncthreads();
    }
    m = red[0]; __syncthreads();

    v.x = __expf(v.x - m); v.y = __expf(v.y - m);
    v.z = __expf(v.z - m); v.w = __expf(v.w - m);
    red[tid] = v.x + v.y + v.z + v.w; __syncthreads();
    for (int o = 128; o > 0; o >>= 1) {
        if (tid < o) red[tid] += red[tid + o];
        __syncthreads();
    }
    float invs = 1.0f / red[0];
    __syncthreads();

    float4 mu4 = ((const float4*)(g_mu  + b * NN))[tid];
    float4 iv4 = ((const float4*)(g_inv + b * NN))[tid];
    float4 w;
    w.x = v.x * invs * iv4.x; w.y = v.y * invs * iv4.y;
    w.z = v.z * invs * iv4.z; w.w = v.w * invs * iv4.w;
    float sacc = w.x * mu4.x + w.y * mu4.y + w.z * mu4.z + w.w * mu4.w;
    w.x = to_tf32(w.x); w.y = to_tf32(w.y);
    w.z = to_tf32(w.z); w.w = to_tf32(w.w);
    p[tid] = w;

    red[tid] = sacc; __syncthreads();
    for (int o = 128; o > 0; o >>= 1) {
        if (tid < o) red[tid] += red[tid + o];
        __syncthreads();
    }
    if (tid == 0) g_s[row] = red[0];
}

// ---- t[b,i,h,r] = gam[ir]*( sum_d u[b,h,i,d]*Wv1T[ir][d] - s[b,h,i] ) + bet[ir] ----
__global__ __launch_bounds__(256) void tfin_kernel(const float* __restrict__ gam,
                                                   const float* __restrict__ bet)
{
    int b = blockIdx.x >> 6, i = blockIdx.x & 63;
    __shared__ float u_s[HH][DD];    // 24 KB
    int tid = threadIdx.x;
    int warp = tid >> 5, lane = tid & 31;

    for (int idx = tid; idx < HH * DD; idx += 256) {
        int h = idx / DD, d = idx % DD;
        u_s[h][d] = g_u[((size_t)b * 512 + h * 64 + i) * DD + d];
    }
    __syncthreads();

    #pragma unroll
    for (int rr = 0; rr < 8; rr++) {
        int r = warp * 8 + rr;
        const float* wv = g_Wv1T + (size_t)(i * RANK + r) * DD;
        float a[8];
        #pragma unroll
        for (int h = 0; h < 8; h++) a[h] = 0.f;
        for (int d = lane; d < DD; d += 32) {
            float wvv = wv[d];
            #pragma unroll
            for (int h = 0; h < 8; h++) a[h] = fmaf(u_s[h][d], wvv, a[h]);
        }
        #pragma unroll
        for (int o = 16; o > 0; o >>= 1)
            #pragma unroll
            for (int h = 0; h < 8; h++) a[h] += __shfl_xor_sync(0xFFFFFFFF, a[h], o);
        if (lane == 0) {
            float gm = gam[i * RANK + r], bt = bet[i * RANK + r];
            #pragma unroll
            for (int h = 0; h < 8; h++) {
                float sv = g_s[(b * HH + h) * NQ + i];
                g_t[((size_t)(b * NQ + i) * HH + h) * RANK + r] = gm * (a[h] - sv) + bt;
            }
        }
    }
}

// ---- out_pre[b,i,d] = sum_r t[b,i,head(d),r]*Wc[i,r,d]  (tf32-rounded write) ------
__global__ __launch_bounds__(256) void conv_kernel(const float* __restrict__ Wc)
{
    int b = blockIdx.x >> 6, i = blockIdx.x & 63;
    __shared__ float ts[HH * RANK];
    int tid = threadIdx.x;
    for (int idx = tid; idx < HH * RANK; idx += 256)
        ts[idx] = g_t[(size_t)(b * NQ + i) * (HH * RANK) + idx];
    __syncthreads();

    for (int dd = tid; dd < DD; dd += 256) {
        int h = dd / DH;
        float acc = 0.f;
        const float* wp = Wc + (size_t)i * RANK * DD + dd;
        #pragma unroll 8
        for (int rr = 0; rr < RANK; rr++)
            acc = fmaf(ts[h * RANK + rr], wp[(size_t)rr * DD], acc);
        g_op[(size_t)(b * NQ + i) * DD + dd] = to_tf32(acc);
    }
}

// ---------------- launch ----------------
#define SMEM128 (3 * (128 * 36 + 32 * 136) * 4)
#define SMEM64  (3 * ( 64 * 36 + 32 * 136) * 4)

extern "C" void kernel_launch(void* const* d_in, const int* in_sizes, int n_in,
                              void* d_out, int out_size)
{
    const float* x       = (const float*)d_in[0];
    const float* context = (const float*)d_in[1];
    const float* Wq      = (const float*)d_in[2];
    const float* Wk      = (const float*)d_in[3];
    const float* Wv1     = (const float*)d_in[4];
    const float* ln_g    = (const float*)d_in[5];
    const float* ln_b    = (const float*)d_in[6];
    const float* Wc      = (const float*)d_in[7];
    const float* Wout    = (const float*)d_in[8];
    float* out = (float*)d_out;

    cudaFuncSetAttribute(tgemm_ca<128>, cudaFuncAttributeMaxDynamicSharedMemorySize, SMEM128);
    cudaFuncSetAttribute(tgemm_ca<64>,  cudaFuncAttributeMaxDynamicSharedMemorySize, SMEM64);
    cudaFuncSetAttribute(simgemm,       cudaFuncAttributeMaxDynamicSharedMemorySize, SIM_SMEM);

    float *pq, *pk, *psim, *pu, *pop, *py, *pGp, *pG32;
    float *pc32, *px32, *pWq, *pWk, *pWv, *pWo, *pWvT;
    cudaGetSymbolAddress((void**)&pq,   g_q);
    cudaGetSymbolAddress((void**)&pk,   g_k);
    cudaGetSymbolAddress((void**)&psim, g_sim);
    cudaGetSymbolAddress((void**)&pu,   g_u);
    cudaGetSymbolAddress((void**)&pop,  g_op);
    cudaGetSymbolAddress((void**)&py,   g_y);
    cudaGetSymbolAddress((void**)&pGp,  g_Gp);
    cudaGetSymbolAddress((void**)&pG32, g_G32);
    cudaGetSymbolAddress((void**)&pc32, g_ctx32);
    cudaGetSymbolAddress((void**)&px32, g_x32);
    cudaGetSymbolAddress((void**)&pWq,  g_Wq32);
    cudaGetSymbolAddress((void**)&pWk,  g_Wk32);
    cudaGetSymbolAddress((void**)&pWv,  g_Wv32);
    cudaGetSymbolAddress((void**)&pWo,  g_Wo32);
    cudaGetSymbolAddress((void**)&pWvT, g_Wv1T);

    // ---- prepass: rounding (one launch), transpose, rowsum ----
    cvt_all<<<8064, 256>>>(context, x, Wq, Wout, Wk, Wv1);
    trans_round<<<dim3(QR / 32, DD / 32), 256>>>(Wv1);
    rowsum<<<DD / 8, 256>>>(Wv1);

    // ---- G = Wv1 @ Wv1^T, split-K (z = 4 chunks of 1024) ----
    tgemm_ca<128><<<dim3(DD / 128, DD / 128, 4), 256, SMEM128>>>(
        pWv, pWvT, pGp, DD, 1024, QR, DD, DD,
        (size_t)1024, (size_t)1024 * DD, (size_t)DD * DD);
    reduce4<<<(DD * DD) / 1024, 256>>>();

    // ---- y = ctx @ G ----
    tgemm_ca<128><<<dim3(DD / 128, (BB * NN) / 128), 256, SMEM128>>>(
        pc32, pG32, py, DD, DD, DD, DD, DD, 0, 0, 0);
    // ---- LN stats from dots ----
    stats<<<(BB * NN) / 8, 256>>>(context);

    // ---- k, q ----
    tgemm_ca<128><<<dim3(DD / 128, (BB * NN) / 128), 256, SMEM128>>>(
        pc32, pWk, pk, DD, DD, DD, DD, DD, 0, 0, 0);
    tgemm_ca<64><<<dim3(DD / 128, (BB * NQ) / 64), 256, SMEM64>>>(
        px32, pWq, pq, DD, DD, DD, DD, DD, 0, 0, 0);

    // ---- attention: logits via tensor cores, then softmax ----
    simgemm<<<dim3(NN / 128, 1, BB * HH), 256, SIM_SMEM>>>();
    softmax_w<<<BB * HH * NQ, 256>>>();

    // ---- u[b, h*64+i, :] = sum_j w * ctx   (z = batch) ----
    tgemm_ca<128><<<dim3(DD / 128, (HH * NQ) / 128, BB), 256, SMEM128>>>(
        psim, pc32, pu, DD, NN, NN, DD, DD,
        (size_t)HH * NQ * NN, (size_t)NN * DD, (size_t)HH * NQ * DD);

    // ---- t, conv, out ----
    tfin_kernel<<<BB * NQ, 256>>>(ln_g, ln_b);
    conv_kernel<<<BB * NQ, 256>>>(Wc);
    tgemm_ca<64><<<dim3(DD / 128, (BB * NQ) / 64), 256, SMEM64>>>(
        pop, pWo, out, DD, DD, DD, DD, DD, 0, 0, 0);
}